// round 15
// baseline (speedup 1.0000x reference)
#include <cuda_runtime.h>

// Fixed shapes for Latency_78632261255775:
//   x: [8, 3, 224, 224] fp32, T = 100
//   out: [8, 100, 3, 224, 224] fp32
#define N_ELEM   1204224        // 8*3*224*224
#define N4       301056         // N_ELEM/4
#define CHW4     37632          // CHW/4 (float4/uchar4 units per image)
#define BATCH    8
#define T_STEPS  100
#define T_PER    20             // time-steps per fill thread (measured best)
#define MM_BLOCKS 1176          // = N4/256 (measured-best minmax shape)
#define FILL_BLOCKS 5880        // 147 * 5 * 8

// Reduction cells live at their identities between runs: statically
// initialized, and reset by the LAST-exiting fill block (strictly after
// every fill block has read them).
__device__ unsigned int g_min_bits = 0xFFFFFFFFu;  // monotone-uint domain
__device__ unsigned int g_max_bits = 0u;
__device__ unsigned int g_fill_exit = 0;

// Order-preserving float <-> uint mapping (monotone for all finite floats).
__device__ __forceinline__ unsigned int f2u(float f) {
    unsigned int u = __float_as_uint(f);
    return (u & 0x80000000u) ? ~u : (u | 0x80000000u);
}
__device__ __forceinline__ float u2f(unsigned int u) {
    u = (u & 0x80000000u) ? (u & 0x7fffffffu) : ~u;
    return __uint_as_float(u);
}

// Kernel 1: min/max (measured-best shape). One float4 per thread, block
// reduce, one fire-and-forget RED.MIN/MAX per block to the global cells.
__global__ void __launch_bounds__(256, 8) minmax_kernel(const float* __restrict__ x) {
    __shared__ unsigned int s_min[8], s_max[8];
    int tid = threadIdx.x;
    int gi = blockIdx.x * 256 + tid;          // 0 .. N4-1
    float4 v = ((const float4*)x)[gi];
    unsigned int a = f2u(v.x), b_ = f2u(v.y), c = f2u(v.z), d = f2u(v.w);
    unsigned int lmin = min(min(a, b_), min(c, d));
    unsigned int lmax = max(max(a, b_), max(c, d));
    #pragma unroll
    for (int off = 16; off > 0; off >>= 1) {
        lmin = min(lmin, __shfl_down_sync(0xFFFFFFFFu, lmin, off));
        lmax = max(lmax, __shfl_down_sync(0xFFFFFFFFu, lmax, off));
    }
    int wid = tid >> 5, lid = tid & 31;
    if (lid == 0) { s_min[wid] = lmin; s_max[wid] = lmax; }
    __syncthreads();
    if (tid < 32) {
        lmin = (lid < 8) ? s_min[lid] : 0xFFFFFFFFu;
        lmax = (lid < 8) ? s_max[lid] : 0u;
        #pragma unroll
        for (int off = 4; off > 0; off >>= 1) {
            lmin = min(lmin, __shfl_down_sync(0xFFFFFFFFu, lmin, off));
            lmax = max(lmax, __shfl_down_sync(0xFFFFFFFFu, lmax, off));
        }
        if (lid == 0) {
            atomicMin(&g_min_bits, lmin);     // REDG (result unused)
            atomicMax(&g_max_bits, lmax);
        }
    }
}

// Kernel 2: fused spike + one-hot fill (R11 structure — measured best),
// with write-through stores (__stwt) instead of evict-first (__stcs):
// pure streaming output, no dirty-line residency / end-of-kernel drain.
// Each thread: compute the 4 spike indices ONCE with the exact reference
// FP sequence (IEEE ops, no fma/reciprocal):
//   xn = (x - min) / ((max - min) + 1e-8)
//   st = clip(trunc((1 - xn) * 99), 0, 99)
// then emit T_PER coalesced float4 stores with inline compare/select.
// Grid (147, 5, 8) = 5880 blocks, 5 waves.
// The LAST-exiting block resets the reduction cells for the next replay.
__global__ void __launch_bounds__(256, 8) fill_kernel(const float* __restrict__ x,
                                                      float* __restrict__ out) {
    int chw4 = blockIdx.x * 256 + threadIdx.x;  // 0 .. CHW4-1
    int t0 = blockIdx.y * T_PER;
    int b = blockIdx.z;
    float mn = u2f(g_min_bits);
    float mx = u2f(g_max_bits);
    float denom = __fadd_rn(__fsub_rn(mx, mn), 1e-8f);
    float4 v = ((const float4*)x)[b * CHW4 + chw4];   // L2-hit after minmax
    int sx, sy, sz, sw;
    {
        float xn = __fdiv_rn(__fsub_rn(v.x, mn), denom);
        sx = max(0, min(99, (int)__fmul_rn(__fsub_rn(1.0f, xn), 99.0f)));
    }
    {
        float xn = __fdiv_rn(__fsub_rn(v.y, mn), denom);
        sy = max(0, min(99, (int)__fmul_rn(__fsub_rn(1.0f, xn), 99.0f)));
    }
    {
        float xn = __fdiv_rn(__fsub_rn(v.z, mn), denom);
        sz = max(0, min(99, (int)__fmul_rn(__fsub_rn(1.0f, xn), 99.0f)));
    }
    {
        float xn = __fdiv_rn(__fsub_rn(v.w, mn), denom);
        sw = max(0, min(99, (int)__fmul_rn(__fsub_rn(1.0f, xn), 99.0f)));
    }
    float4* base = (float4*)out + (size_t)(b * T_STEPS + t0) * CHW4 + chw4;
    #pragma unroll
    for (int k = 0; k < T_PER; k++) {
        int t = t0 + k;
        float4 o;
        o.x = (sx == t) ? 1.0f : 0.0f;
        o.y = (sy == t) ? 1.0f : 0.0f;
        o.z = (sz == t) ? 1.0f : 0.0f;
        o.w = (sw == t) ? 1.0f : 0.0f;
        __stwt(base + (size_t)k * CHW4, o);          // write-through
    }
    // Replay-safe reset: last block to finish (all blocks have already read
    // g_min_bits/g_max_bits at their start, before their exit increment).
    if (threadIdx.x == 0) {
        __threadfence();
        unsigned int prev = atomicAdd(&g_fill_exit, 1u);
        if (prev == FILL_BLOCKS - 1) {
            g_min_bits = 0xFFFFFFFFu;
            g_max_bits = 0u;
            g_fill_exit = 0;
        }
    }
}

extern "C" void kernel_launch(void* const* d_in, const int* in_sizes, int n_in,
                              void* d_out, int out_size) {
    const float* x = (const float*)d_in[0];
    float* out = (float*)d_out;

    minmax_kernel<<<MM_BLOCKS, 256>>>(x);
    dim3 fgrid(CHW4 / 256, T_STEPS / T_PER, BATCH);   // (147, 5, 8)
    fill_kernel<<<fgrid, 256>>>(x, out);
}

// round 16
// speedup vs baseline: 1.0683x; 1.0683x over previous
#include <cuda_runtime.h>

// Fixed shapes for Latency_78632261255775:
//   x: [8, 3, 224, 224] fp32, T = 100
//   out: [8, 100, 3, 224, 224] fp32
#define N_ELEM   1204224        // 8*3*224*224
#define N4       301056         // N_ELEM/4
#define CHW4     37632          // CHW/4 (float4/uchar4 units per image)
#define BATCH    8
#define T_STEPS  100
#define T_PER    20             // time-steps per fill thread (measured best)
#define MM_BLOCKS 1176          // = N4/256 (measured-best minmax shape)
#define FILL_BLOCKS 5880        // 147 * 5 * 8

// Reduction cells live at their identities between runs: statically
// initialized, and reset by the LAST-exiting fill block (strictly after
// every fill block has read them).
__device__ unsigned int g_min_bits = 0xFFFFFFFFu;  // monotone-uint domain
__device__ unsigned int g_max_bits = 0u;
__device__ unsigned int g_fill_exit = 0;

// Order-preserving float <-> uint mapping (monotone for all finite floats).
__device__ __forceinline__ unsigned int f2u(float f) {
    unsigned int u = __float_as_uint(f);
    return (u & 0x80000000u) ? ~u : (u | 0x80000000u);
}
__device__ __forceinline__ float u2f(unsigned int u) {
    u = (u & 0x80000000u) ? (u & 0x7fffffffu) : ~u;
    return __uint_as_float(u);
}

// Kernel 1: min/max (measured-best shape). One float4 per thread, block
// reduce, one fire-and-forget RED.MIN/MAX per block to the global cells.
// Measured at ~5us — a replay-ramp/launch floor, shape-invariant across
// grid-stride, 1-wave, MLP=4 and fused variants.
__global__ void __launch_bounds__(256, 8) minmax_kernel(const float* __restrict__ x) {
    __shared__ unsigned int s_min[8], s_max[8];
    int tid = threadIdx.x;
    int gi = blockIdx.x * 256 + tid;          // 0 .. N4-1
    float4 v = ((const float4*)x)[gi];
    unsigned int a = f2u(v.x), b_ = f2u(v.y), c = f2u(v.z), d = f2u(v.w);
    unsigned int lmin = min(min(a, b_), min(c, d));
    unsigned int lmax = max(max(a, b_), max(c, d));
    #pragma unroll
    for (int off = 16; off > 0; off >>= 1) {
        lmin = min(lmin, __shfl_down_sync(0xFFFFFFFFu, lmin, off));
        lmax = max(lmax, __shfl_down_sync(0xFFFFFFFFu, lmax, off));
    }
    int wid = tid >> 5, lid = tid & 31;
    if (lid == 0) { s_min[wid] = lmin; s_max[wid] = lmax; }
    __syncthreads();
    if (tid < 32) {
        lmin = (lid < 8) ? s_min[lid] : 0xFFFFFFFFu;
        lmax = (lid < 8) ? s_max[lid] : 0u;
        #pragma unroll
        for (int off = 4; off > 0; off >>= 1) {
            lmin = min(lmin, __shfl_down_sync(0xFFFFFFFFu, lmin, off));
            lmax = max(lmax, __shfl_down_sync(0xFFFFFFFFu, lmax, off));
        }
        if (lid == 0) {
            atomicMin(&g_min_bits, lmin);     // REDG (result unused)
            atomicMax(&g_max_bits, lmax);
        }
    }
}

// Kernel 2: fused spike + one-hot fill — the measured-best configuration
// (72.8us total). Each thread: read min/max cells, load its float4 of x
// (L2-hit after minmax), compute the 4 spike indices ONCE with the exact
// reference FP sequence (IEEE ops, no fma/reciprocal):
//   xn = (x - min) / ((max - min) + 1e-8)
//   st = clip(trunc((1 - xn) * 99), 0, 99)
// then emit T_PER coalesced evict-first (__stcs) float4 stores with inline
// compare/select. Measured-out alternatives: zero-stream+overwrite (RMW on
// streamed lines), __stwt (defeats L2 write coalescing), T_PER {10,25,100},
// PDL, persistent kernel — all slower.
// Grid (147, 5, 8) = 5880 blocks, 5 waves of backfill.
// The LAST-exiting block resets the reduction cells for the next replay.
__global__ void __launch_bounds__(256, 8) fill_kernel(const float* __restrict__ x,
                                                      float* __restrict__ out) {
    int chw4 = blockIdx.x * 256 + threadIdx.x;  // 0 .. CHW4-1
    int t0 = blockIdx.y * T_PER;
    int b = blockIdx.z;
    float mn = u2f(g_min_bits);
    float mx = u2f(g_max_bits);
    float denom = __fadd_rn(__fsub_rn(mx, mn), 1e-8f);
    float4 v = ((const float4*)x)[b * CHW4 + chw4];   // L2-hit after minmax
    int sx, sy, sz, sw;
    {
        float xn = __fdiv_rn(__fsub_rn(v.x, mn), denom);
        sx = max(0, min(99, (int)__fmul_rn(__fsub_rn(1.0f, xn), 99.0f)));
    }
    {
        float xn = __fdiv_rn(__fsub_rn(v.y, mn), denom);
        sy = max(0, min(99, (int)__fmul_rn(__fsub_rn(1.0f, xn), 99.0f)));
    }
    {
        float xn = __fdiv_rn(__fsub_rn(v.z, mn), denom);
        sz = max(0, min(99, (int)__fmul_rn(__fsub_rn(1.0f, xn), 99.0f)));
    }
    {
        float xn = __fdiv_rn(__fsub_rn(v.w, mn), denom);
        sw = max(0, min(99, (int)__fmul_rn(__fsub_rn(1.0f, xn), 99.0f)));
    }
    float4* base = (float4*)out + (size_t)(b * T_STEPS + t0) * CHW4 + chw4;
    #pragma unroll
    for (int k = 0; k < T_PER; k++) {
        int t = t0 + k;
        float4 o;
        o.x = (sx == t) ? 1.0f : 0.0f;
        o.y = (sy == t) ? 1.0f : 0.0f;
        o.z = (sz == t) ? 1.0f : 0.0f;
        o.w = (sw == t) ? 1.0f : 0.0f;
        __stcs(base + (size_t)k * CHW4, o);
    }
    // Replay-safe reset: last block to finish (all blocks have already read
    // g_min_bits/g_max_bits at their start, before their exit increment).
    if (threadIdx.x == 0) {
        __threadfence();
        unsigned int prev = atomicAdd(&g_fill_exit, 1u);
        if (prev == FILL_BLOCKS - 1) {
            g_min_bits = 0xFFFFFFFFu;
            g_max_bits = 0u;
            g_fill_exit = 0;
        }
    }
}

extern "C" void kernel_launch(void* const* d_in, const int* in_sizes, int n_in,
                              void* d_out, int out_size) {
    const float* x = (const float*)d_in[0];
    float* out = (float*)d_out;

    minmax_kernel<<<MM_BLOCKS, 256>>>(x);
    dim3 fgrid(CHW4 / 256, T_STEPS / T_PER, BATCH);   // (147, 5, 8)
    fill_kernel<<<fgrid, 256>>>(x, out);
}

// round 17
// speedup vs baseline: 1.0706x; 1.0022x over previous
#include <cuda_runtime.h>

// Fixed shapes for Latency_78632261255775:
//   x: [8, 3, 224, 224] fp32, T = 100
//   out: [8, 100, 3, 224, 224] fp32
#define N_ELEM   1204224        // 8*3*224*224
#define N4       301056         // N_ELEM/4
#define CHW4     37632          // CHW/4 (float4/uchar4 units per image)
#define BATCH    8
#define T_STEPS  100
#define T_PER    20             // time-steps per fill thread (measured best)
#define MM_BLOCKS 1176          // = N4/256 (measured-best minmax shape)
#define FILL_TPB  128           // fill threads per block (this round's variable)
#define FILL_BX   294           // CHW4 / FILL_TPB
#define FILL_BLOCKS 11760       // 294 * 5 * 8

// Reduction cells live at their identities between runs: statically
// initialized, and reset by the LAST-exiting fill block (strictly after
// every fill block has read them).
__device__ unsigned int g_min_bits = 0xFFFFFFFFu;  // monotone-uint domain
__device__ unsigned int g_max_bits = 0u;
__device__ unsigned int g_fill_exit = 0;

// Order-preserving float <-> uint mapping (monotone for all finite floats).
__device__ __forceinline__ unsigned int f2u(float f) {
    unsigned int u = __float_as_uint(f);
    return (u & 0x80000000u) ? ~u : (u | 0x80000000u);
}
__device__ __forceinline__ float u2f(unsigned int u) {
    u = (u & 0x80000000u) ? (u & 0x7fffffffu) : ~u;
    return __uint_as_float(u);
}

// Kernel 1: min/max (measured-best shape). One float4 per thread, block
// reduce, one fire-and-forget RED.MIN/MAX per block to the global cells.
// ~5us = replay-ramp/launch floor, shape-invariant (4 experiments).
__global__ void __launch_bounds__(256, 8) minmax_kernel(const float* __restrict__ x) {
    __shared__ unsigned int s_min[8], s_max[8];
    int tid = threadIdx.x;
    int gi = blockIdx.x * 256 + tid;          // 0 .. N4-1
    float4 v = ((const float4*)x)[gi];
    unsigned int a = f2u(v.x), b_ = f2u(v.y), c = f2u(v.z), d = f2u(v.w);
    unsigned int lmin = min(min(a, b_), min(c, d));
    unsigned int lmax = max(max(a, b_), max(c, d));
    #pragma unroll
    for (int off = 16; off > 0; off >>= 1) {
        lmin = min(lmin, __shfl_down_sync(0xFFFFFFFFu, lmin, off));
        lmax = max(lmax, __shfl_down_sync(0xFFFFFFFFu, lmax, off));
    }
    int wid = tid >> 5, lid = tid & 31;
    if (lid == 0) { s_min[wid] = lmin; s_max[wid] = lmax; }
    __syncthreads();
    if (tid < 32) {
        lmin = (lid < 8) ? s_min[lid] : 0xFFFFFFFFu;
        lmax = (lid < 8) ? s_max[lid] : 0u;
        #pragma unroll
        for (int off = 4; off > 0; off >>= 1) {
            lmin = min(lmin, __shfl_down_sync(0xFFFFFFFFu, lmin, off));
            lmax = max(lmax, __shfl_down_sync(0xFFFFFFFFu, lmax, off));
        }
        if (lid == 0) {
            atomicMin(&g_min_bits, lmin);     // REDG (result unused)
            atomicMax(&g_max_bits, lmax);
        }
    }
}

// Kernel 2: fused spike + one-hot fill (winning R11 structure), with
// 128-thread blocks (untested axis): full occupancy retained
// (16 blocks/SM x 128 = 2048 thr), 2x finer tail/wave granularity, more
// distinct (b,t0) store streams interleaved per SM.
// Exact reference FP sequence (IEEE ops, no fma/reciprocal):
//   xn = (x - min) / ((max - min) + 1e-8)
//   st = clip(trunc((1 - xn) * 99), 0, 99)
// T_PER coalesced evict-first (__stcs) float4 stores with inline cmp/sel.
// The LAST-exiting block resets the reduction cells for the next replay.
__global__ void __launch_bounds__(FILL_TPB, 16) fill_kernel(const float* __restrict__ x,
                                                            float* __restrict__ out) {
    int chw4 = blockIdx.x * FILL_TPB + threadIdx.x;  // 0 .. CHW4-1
    int t0 = blockIdx.y * T_PER;
    int b = blockIdx.z;
    float mn = u2f(g_min_bits);
    float mx = u2f(g_max_bits);
    float denom = __fadd_rn(__fsub_rn(mx, mn), 1e-8f);
    float4 v = ((const float4*)x)[b * CHW4 + chw4];   // L2-hit after minmax
    int sx, sy, sz, sw;
    {
        float xn = __fdiv_rn(__fsub_rn(v.x, mn), denom);
        sx = max(0, min(99, (int)__fmul_rn(__fsub_rn(1.0f, xn), 99.0f)));
    }
    {
        float xn = __fdiv_rn(__fsub_rn(v.y, mn), denom);
        sy = max(0, min(99, (int)__fmul_rn(__fsub_rn(1.0f, xn), 99.0f)));
    }
    {
        float xn = __fdiv_rn(__fsub_rn(v.z, mn), denom);
        sz = max(0, min(99, (int)__fmul_rn(__fsub_rn(1.0f, xn), 99.0f)));
    }
    {
        float xn = __fdiv_rn(__fsub_rn(v.w, mn), denom);
        sw = max(0, min(99, (int)__fmul_rn(__fsub_rn(1.0f, xn), 99.0f)));
    }
    float4* base = (float4*)out + (size_t)(b * T_STEPS + t0) * CHW4 + chw4;
    #pragma unroll
    for (int k = 0; k < T_PER; k++) {
        int t = t0 + k;
        float4 o;
        o.x = (sx == t) ? 1.0f : 0.0f;
        o.y = (sy == t) ? 1.0f : 0.0f;
        o.z = (sz == t) ? 1.0f : 0.0f;
        o.w = (sw == t) ? 1.0f : 0.0f;
        __stcs(base + (size_t)k * CHW4, o);
    }
    // Replay-safe reset: last block to finish (all blocks have already read
    // g_min_bits/g_max_bits at their start, before their exit increment).
    if (threadIdx.x == 0) {
        __threadfence();
        unsigned int prev = atomicAdd(&g_fill_exit, 1u);
        if (prev == FILL_BLOCKS - 1) {
            g_min_bits = 0xFFFFFFFFu;
            g_max_bits = 0u;
            g_fill_exit = 0;
        }
    }
}

extern "C" void kernel_launch(void* const* d_in, const int* in_sizes, int n_in,
                              void* d_out, int out_size) {
    const float* x = (const float*)d_in[0];
    float* out = (float*)d_out;

    minmax_kernel<<<MM_BLOCKS, 256>>>(x);
    dim3 fgrid(FILL_BX, T_STEPS / T_PER, BATCH);   // (294, 5, 8)
    fill_kernel<<<fgrid, FILL_TPB>>>(x, out);
}